// round 12
// baseline (speedup 1.0000x reference)
#include <cuda_runtime.h>
#include <cuda_fp16.h>
#include <cstdint>

#define BB 32
#define TT 512
#define KK 48
#define SROW 56              // (24u + 2c + 8w) banks: conflict-free per 16-lane phase
#define TILESZ (KK * SROW)   // 2688
#define NTH 192              // 6 warps
#define NB 6
#define START_TAG 46
#define STOP_TAG 47

__device__ float g_partials[BB];
__device__ int   g_ctr = 0;

__device__ __forceinline__ float ex2f(float x) {
    float y; asm("ex2.approx.ftz.f32 %0, %1;" : "=f"(y) : "f"(x)); return y;
}
__device__ __forceinline__ float lg2f(float x) {
    float y; asm("lg2.approx.ftz.f32 %0, %1;" : "=f"(y) : "f"(x)); return y;
}
__device__ __forceinline__ void cp16(uint32_t smem, const void* g) {
    asm volatile("cp.async.cg.shared.global [%0], [%1], 16;" :: "r"(smem), "l"(g));
}
__device__ __forceinline__ void cp_commit() { asm volatile("cp.async.commit_group;"); }
__device__ __forceinline__ void cp_wait3()  { asm volatile("cp.async.wait_group 3;"); }
__device__ __forceinline__ void cp_wait4()  { asm volatile("cp.async.wait_group 4;"); }

// pack two fp32 (already ×log2e) and take 2^x via one MUFU op; result stays f16x2
__device__ __forceinline__ uint32_t ex2_pack(float f0, float f1) {
    uint32_t p, r;
    asm("cvt.rn.f16x2.f32 %0, %1, %2;" : "=r"(p) : "f"(f1), "f"(f0));  // hi=f1, lo=f0
    asm volatile("ex2.approx.f16x2 %0, %1;" : "=r"(r) : "r"(p));
    return r;
}
__device__ __forceinline__ uint32_t hfma2(uint32_t a, uint32_t b, uint32_t c) {
    uint32_t d; asm("fma.rn.f16x2 %0, %1, %2, %3;" : "=r"(d) : "r"(a), "r"(b), "r"(c)); return d;
}
__device__ __forceinline__ uint32_t hmul2(uint32_t a, uint32_t b) {
    uint32_t d; asm("mul.f16x2 %0, %1, %2;" : "=r"(d) : "r"(a), "r"(b)); return d;
}
__device__ __forceinline__ uint32_t hadd2(uint32_t a, uint32_t b) {
    uint32_t d; asm("add.f16x2 %0, %1, %2;" : "=r"(d) : "r"(a), "r"(b)); return d;
}
__device__ __forceinline__ uint32_t prmt(uint32_t a, uint32_t sel) {
    uint32_t d; asm("prmt.b32 %0, %1, %1, %2;" : "=r"(d) : "r"(a), "r"(sel)); return d;
}

extern __shared__ float smem_dyn[];

__global__ __launch_bounds__(NTH, 1)
void crf_fwd_kernel(const float* __restrict__ feat,
                    const int*   __restrict__ targets,
                    const int*   __restrict__ lengths,
                    float*       __restrict__ out)
{
    float*    tile = smem_dyn;                         // NB * TILESZ fp32
    float*    cF   = tile + NB * TILESZ;               // 2 x 48 fp32 carries
    uint32_t* ch   = (uint32_t*)(cF + 2 * KK);         // 2 x 48 packed (c,c) f16x2, x2^-4
    int*      tsh  = (int*)(ch + 2 * KK);              // TT

    const int b   = blockIdx.x;
    const int tid = threadIdx.x;
    const int len = lengths[b];
    const float* fb = feat + (size_t)b * TT * (KK * KK);

    for (int i = tid; i < TT; i += NTH) {
        int v = targets[b * TT + i];
        tsh[i] = (v / KK) * SROW + (v % KK);
    }

    // lane owns column pair p = 4w + (l&3), columns j0=2p, j0+1; i = u + 8*ii, u = l>>2
    const int l = tid & 31;
    const int w = tid >> 5;
    const int p = 4 * w + (l & 3);
    const int u = l >> 2;

    // prefetch chunks: exactly 3 per thread (576 = 3*192)
    uint32_t so[3]; size_t go[3];
    #pragma unroll
    for (int q = 0; q < 3; ++q) {
        int k = tid + q * NTH;
        so[q] = (uint32_t)((k / 12) * SROW * 4 + (k % 12) * 16);
        go[q] = (size_t)(k / 12) * KK + (size_t)(k % 12) * 4;
    }
    uint32_t sb[NB];
    #pragma unroll
    for (int n = 0; n < NB; ++n)
        sb[n] = (uint32_t)__cvta_generic_to_shared(tile + n * TILESZ);

    const float LOG2E = 1.4426950408889634f;
    const float LN2   = 0.6931471805599453f;
    const float SC    = 0.0625f;               // 2^-4 headroom for fp16 packed carries

    // Prologue: issue tiles 0..4 as 5 groups
    #pragma unroll
    for (int tt = 0; tt < 5; ++tt) {
        if (tt < len) {
            const float* src = fb + (size_t)tt * (KK * KK);
            #pragma unroll
            for (int q = 0; q < 3; ++q) cp16(sb[tt] + so[q], src + go[q]);
        }
        cp_commit();
    }
    cp_wait4();
    __syncthreads();       // tile 0 visible

    // init carries into buffer 0 (fp32 exact + packed f16x2 with 2^-4 scale)
    if (tid < KK) {
        float c = ex2f(tile[SROW * START_TAG + tid] * LOG2E);
        cF[tid] = c;
        __half h = __float2half_rn(c * SC);
        uint32_t hb = (uint32_t)__half_as_ushort(h);
        ch[tid] = hb | (hb << 16);
    }
    float gold = 0.f;
    int   eacc = 0;
    if (tid == 0) gold = tile[tsh[0]];

    cp_wait3();
    __syncthreads();       // tile 1 visible

    // E for tile 1 (12 elements = 6 packed f16x2)
    uint32_t E2[6];
    {
        const float* fn = tile + 1 * TILESZ + u * SROW + 2 * p;
        #pragma unroll
        for (int ii = 0; ii < 6; ++ii) {
            float2 f = *(const float2*)(fn + SROW * 8 * ii);
            E2[ii] = ex2_pack(f.x * LOG2E, f.y * LOG2E);
        }
    }
    if (5 < len) {
        const float* src = fb + (size_t)5 * (KK * KK);
        #pragma unroll
        for (int q = 0; q < 3; ++q) cp16(sb[5] + so[q], src + go[q]);
    }
    cp_commit();

    int cur = 1;   // t % NB
    int pfb = 0;   // (t+5) % NB
    for (int t = 1; t < len; ++t) {
        cp_wait3();
        __syncthreads();     // carries(t-1) + tile t+1 visible; buffer pfb drained

        // prefetch tile t+5
        {
            int tn = t + 5;
            if (tn < len) {
                const float* src = fb + (size_t)tn * (KK * KK);
                uint32_t dst = sb[pfb];
                #pragma unroll
                for (int q = 0; q < 3; ++q) cp16(dst + so[q], src + go[q]);
            }
            cp_commit();
        }

        const int prev = (t - 1) & 1;
        const float c0 = cF[prev * KK];
        const uint32_t cb = __float_as_uint(c0);
        const int      be = (int)(cb >> 23);
        const float    rsc = __uint_as_float((uint32_t)(254 - be) << 23);  // 2^-(be-127)

        // dot product over i for both columns at once (f16x2)
        const uint32_t* cr = ch + prev * KK;
        uint32_t C0 = cr[u];
        uint32_t C1 = cr[u + 8];
        uint32_t C2 = cr[u + 16];
        uint32_t C3 = cr[u + 24];
        uint32_t C4 = cr[u + 32];
        uint32_t C5 = cr[u + 40];
        uint32_t aa = hmul2(E2[0], C0);
        uint32_t bb = hmul2(E2[1], C1);
        aa = hfma2(E2[2], C2, aa);
        bb = hfma2(E2[3], C3, bb);
        aa = hfma2(E2[4], C4, aa);
        bb = hfma2(E2[5], C5, bb);
        uint32_t acc = hadd2(aa, bb);

        if (tid == 0) {
            eacc += be - 127;
            gold += tile[cur * TILESZ + tsh[t]];
        }

        // E for tile t+1 (pinned EX2 pre-barrier; dead at t = len-1, harmless)
        {
            const float* fn = tile + ((cur + 1 == NB) ? 0 : cur + 1) * TILESZ + u * SROW + 2 * p;
            #pragma unroll
            for (int ii = 0; ii < 6; ++ii) {
                float2 f = *(const float2*)(fn + SROW * 8 * ii);
                E2[ii] = ex2_pack(f.x * LOG2E, f.y * LOG2E);
            }
        }

        // reduce over u (8 lanes), both columns simultaneously
        acc = hadd2(acc, __shfl_xor_sync(0xffffffffu, acc, 4));
        acc = hadd2(acc, __shfl_xor_sync(0xffffffffu, acc, 8));
        acc = hadd2(acc, __shfl_xor_sync(0xffffffffu, acc, 16));

        if (u == 0) {
            // unpack, renormalize, store fp32 + packed-scaled f16x2
            float flo, fhi;
            asm("{.reg .f16 lo, hi;\n\t"
                " mov.b32 {lo, hi}, %2;\n\t"
                " cvt.f32.f16 %0, lo;\n\t"
                " cvt.f32.f16 %1, hi;}"
                : "=f"(flo), "=f"(fhi) : "r"(acc));
            float gl = flo * rsc;
            float gh = fhi * rsc;
            *(float2*)(cF + (t & 1) * KK + 2 * p) = make_float2(gl, gh);
            uint32_t pk;
            float sl = gl * SC, sh = gh * SC;
            asm("cvt.rn.f16x2.f32 %0, %1, %2;" : "=r"(pk) : "f"(sh), "f"(sl));
            uint32_t d0 = prmt(pk, 0x1010);   // (lo,lo)
            uint32_t d1 = prmt(pk, 0x3232);   // (hi,hi)
            *(uint2*)(ch + (t & 1) * KK + 2 * p) = make_uint2(d0, d1);
        }

        if (++cur == NB) cur = 0;
        if (++pfb == NB) pfb = 0;
    }

    __syncthreads();
    if (tid == 0) {
        float fin = ((float)eacc + 4.0f * (float)(len - 1)
                     + lg2f(cF[((len - 1) & 1) * KK + STOP_TAG])) * LN2;
        g_partials[b] = fin - gold;
    }

    // fused deterministic batch reduction (last block)
    if (tid < 32) {
        int old = 0;
        if (tid == 0) {
            __threadfence();
            old = atomicAdd(&g_ctr, 1);
        }
        old = __shfl_sync(0xffffffffu, old, 0);
        if (old == BB - 1) {
            __threadfence();
            float v = g_partials[tid];
            #pragma unroll
            for (int o = 16; o; o >>= 1) v += __shfl_down_sync(0xffffffffu, v, o);
            if (tid == 0) { out[0] = v / (float)BB; g_ctr = 0; }
        }
    }
}

extern "C" void kernel_launch(void* const* d_in, const int* in_sizes, int n_in,
                              void* d_out, int out_size)
{
    const float* feat    = (const float*)d_in[0];
    const int*   targets = (const int*)d_in[1];
    const int*   lengths = (const int*)d_in[2];
    float*       out     = (float*)d_out;

    const int smem_bytes = (NB * TILESZ + 2 * KK) * 4 + 2 * KK * 4 + TT * 4;  // ~67 KB
    cudaFuncSetAttribute(crf_fwd_kernel, cudaFuncAttributeMaxDynamicSharedMemorySize, smem_bytes);
    crf_fwd_kernel<<<BB, NTH, smem_bytes>>>(feat, targets, lengths, out);
}

// round 14
// speedup vs baseline: 1.1126x; 1.1126x over previous
#include <cuda_runtime.h>
#include <cuda_fp16.h>
#include <cstdint>

#define BB 32
#define TT 512
#define KK 48
#define SROW 56              // LDS.64 banks (24u + 8w + 2c) conflict-free per phase
#define TILESZ (KK * SROW)   // 2688
#define NTH 192              // 6 warps
#define NB 6
#define START_TAG 46
#define STOP_TAG 47

__device__ float g_partials[BB];
__device__ int   g_ctr = 0;

__device__ __forceinline__ float ex2f(float x) {
    float y; asm("ex2.approx.ftz.f32 %0, %1;" : "=f"(y) : "f"(x)); return y;
}
__device__ __forceinline__ float lg2f(float x) {
    float y; asm("lg2.approx.ftz.f32 %0, %1;" : "=f"(y) : "f"(x)); return y;
}
__device__ __forceinline__ void cp16(uint32_t smem, const void* g) {
    asm volatile("cp.async.cg.shared.global [%0], [%1], 16;" :: "r"(smem), "l"(g));
}
__device__ __forceinline__ void cp_commit() { asm volatile("cp.async.commit_group;"); }
__device__ __forceinline__ void cp_wait3()  { asm volatile("cp.async.wait_group 3;"); }
__device__ __forceinline__ void cp_wait4()  { asm volatile("cp.async.wait_group 4;"); }

// pack two fp32 to f16x2, multiply by log2e in half, then 2^x via one MUFU op
__device__ __forceinline__ uint32_t ex2_cvt(float f0, float f1, uint32_t l2e2) {
    uint32_t p, r;
    asm("cvt.rn.f16x2.f32 %0, %1, %2;" : "=r"(p) : "f"(f1), "f"(f0));  // hi=f1, lo=f0
    asm("mul.f16x2 %0, %0, %1;" : "+r"(p) : "r"(l2e2));
    asm volatile("ex2.approx.f16x2 %0, %1;" : "=r"(r) : "r"(p));
    return r;
}
__device__ __forceinline__ uint32_t hfma2(uint32_t a, uint32_t b, uint32_t c) {
    uint32_t d; asm("fma.rn.f16x2 %0, %1, %2, %3;" : "=r"(d) : "r"(a), "r"(b), "r"(c)); return d;
}
__device__ __forceinline__ uint32_t hmul2(uint32_t a, uint32_t b) {
    uint32_t d; asm("mul.f16x2 %0, %1, %2;" : "=r"(d) : "r"(a), "r"(b)); return d;
}
__device__ __forceinline__ uint32_t hadd2(uint32_t a, uint32_t b) {
    uint32_t d; asm("add.f16x2 %0, %1, %2;" : "=r"(d) : "r"(a), "r"(b)); return d;
}
__device__ __forceinline__ uint32_t prmt(uint32_t a, uint32_t sel) {
    uint32_t d; asm("prmt.b32 %0, %1, %1, %2;" : "=r"(d) : "r"(a), "r"(sel)); return d;
}

extern __shared__ float smem_dyn[];

__global__ __launch_bounds__(NTH, 1)
void crf_fwd_kernel(const float* __restrict__ feat,
                    const int*   __restrict__ targets,
                    const int*   __restrict__ lengths,
                    float*       __restrict__ out)
{
    float*    tile = smem_dyn;                         // NB * TILESZ fp32
    uint32_t* ch   = (uint32_t*)(tile + NB * TILESZ);  // 2 x 48 packed (c,c) f16x2
    int*      tsh  = (int*)(ch + 2 * KK);              // TT

    const int b   = blockIdx.x;
    const int tid = threadIdx.x;
    const int len = lengths[b];
    const float* fb = feat + (size_t)b * TT * (KK * KK);

    for (int i = tid; i < TT; i += NTH) {
        int v = targets[b * TT + i];
        tsh[i] = (v / KK) * SROW + (v % KK);
    }

    // lane owns column pair p = 4w + (l&3) -> cols 2p, 2p+1; i = u + 8*ii, u = l>>2
    const int l = tid & 31;
    const int w = tid >> 5;
    const int p = 4 * w + (l & 3);
    const int u = l >> 2;

    const uint32_t L2E2 = 0x3DC53DC5u;   // half(log2e) duplicated

    // prefetch chunks: exactly 3 per thread (576 = 3*192)
    uint32_t so[3]; size_t go[3];
    #pragma unroll
    for (int q = 0; q < 3; ++q) {
        int k = tid + q * NTH;
        so[q] = (uint32_t)((k / 12) * SROW * 4 + (k % 12) * 16);
        go[q] = (size_t)(k / 12) * KK + (size_t)(k % 12) * 4;
    }
    uint32_t sb[NB];
    #pragma unroll
    for (int n = 0; n < NB; ++n)
        sb[n] = (uint32_t)__cvta_generic_to_shared(tile + n * TILESZ);

    const float LN2 = 0.6931471805599453f;

    // Prologue: issue tiles 0..4 as 5 groups
    #pragma unroll
    for (int tt = 0; tt < 5; ++tt) {
        if (tt < len) {
            const float* src = fb + (size_t)tt * (KK * KK);
            #pragma unroll
            for (int q = 0; q < 3; ++q) cp16(sb[tt] + so[q], src + go[q]);
        }
        cp_commit();
    }
    cp_wait4();
    __syncthreads();       // tile 0 visible

    // init packed carries s_0 = c_0 * 2^-4  (N_0 = 2^4), buffer 0
    if (tid < KK) {
        float c = ex2f(tile[SROW * START_TAG + tid] * 1.4426950408889634f);
        __half h = __float2half_rn(c * 0.0625f);
        uint32_t hb = (uint32_t)__half_as_ushort(h);
        ch[tid] = hb | (hb << 16);
    }
    float gold = 0.f;
    int   eacc = 0;
    if (tid == 0) gold = tile[tsh[0]];

    cp_wait3();
    __syncthreads();       // tile 1 visible

    // E for tile 1 (12 elements = 6 packed f16x2)
    uint32_t E2[6];
    {
        const float* fn = tile + 1 * TILESZ + u * SROW + 2 * p;
        #pragma unroll
        for (int ii = 0; ii < 6; ++ii) {
            float2 f = *(const float2*)(fn + SROW * 8 * ii);
            E2[ii] = ex2_cvt(f.x, f.y, L2E2);
        }
    }
    if (5 < len) {
        const float* src = fb + (size_t)5 * (KK * KK);
        #pragma unroll
        for (int q = 0; q < 3; ++q) cp16(sb[5] + so[q], src + go[q]);
    }
    cp_commit();

    int cur = 1;   // t % NB
    int pfb = 0;   // (t+5) % NB
    for (int t = 1; t < len; ++t) {
        cp_wait3();
        __syncthreads();     // carries(t-1) + tile t+1 visible; buffer pfb drained

        // prefetch tile t+5
        {
            int tn = t + 5;
            if (tn < len) {
                const float* src = fb + (size_t)tn * (KK * KK);
                uint32_t dst = sb[pfb];
                #pragma unroll
                for (int q = 0; q < 3; ++q) cp16(dst + so[q], src + go[q]);
            }
            cp_commit();
        }

        const int prev = (t - 1) & 1;
        const uint32_t* cr = ch + prev * KK;

        // lagged renorm, target T = -8: rsc = 2^(-8 - (be-15)); f16 field = 22 - be
        const uint32_t ch0 = cr[0];
        const int be = (int)((ch0 >> 10) & 31);
        const uint32_t rb = (uint32_t)(22 - be) << 10;
        const uint32_t rsc2 = rb | (rb << 16);
        eacc += be;

        // dot product over i for both columns at once (f16x2)
        uint32_t C0 = cr[u];
        uint32_t C1 = cr[u + 8];
        uint32_t C2 = cr[u + 16];
        uint32_t C3 = cr[u + 24];
        uint32_t C4 = cr[u + 32];
        uint32_t C5 = cr[u + 40];
        uint32_t aa = hmul2(E2[0], C0);
        uint32_t bb = hmul2(E2[1], C1);
        aa = hfma2(E2[2], C2, aa);
        bb = hfma2(E2[3], C3, bb);
        aa = hfma2(E2[4], C4, aa);
        bb = hfma2(E2[5], C5, bb);
        uint32_t acc = hadd2(aa, bb);

        if (tid == 0) gold += tile[cur * TILESZ + tsh[t]];

        // E for tile t+1 (pinned EX2 pre-barrier; dead at t = len-1, harmless)
        {
            const float* fn = tile + ((cur + 1 == NB) ? 0 : cur + 1) * TILESZ + u * SROW + 2 * p;
            #pragma unroll
            for (int ii = 0; ii < 6; ++ii) {
                float2 f = *(const float2*)(fn + SROW * 8 * ii);
                E2[ii] = ex2_cvt(f.x, f.y, L2E2);
            }
        }

        // reduce over u (8 lanes), both columns simultaneously
        acc = hadd2(acc, __shfl_xor_sync(0xffffffffu, acc, 4));
        acc = hadd2(acc, __shfl_xor_sync(0xffffffffu, acc, 8));
        acc = hadd2(acc, __shfl_xor_sync(0xffffffffu, acc, 16));

        if (u == 0) {
            // stay packed: scale, duplicate halves, one 8-byte store
            acc = hmul2(acc, rsc2);
            uint32_t d0 = prmt(acc, 0x1010);   // (lo,lo) -> col 2p
            uint32_t d1 = prmt(acc, 0x3232);   // (hi,hi) -> col 2p+1
            *(uint2*)(ch + (t & 1) * KK + 2 * p) = make_uint2(d0, d1);
        }

        if (++cur == NB) cur = 0;
        if (++pfb == NB) pfb = 0;
    }

    __syncthreads();
    if (tid == 0) {
        // ledger: lg2(c_last[stop]) = lg2(s_last[stop]) + 4 + sum(be) - 7*(len-1)
        uint32_t sw = ch[((len - 1) & 1) * KK + STOP_TAG];
        float s = __half2float(__ushort_as_half((unsigned short)(sw & 0xFFFF)));
        float fin = (lg2f(s) + 4.0f + (float)eacc - 7.0f * (float)(len - 1)) * LN2;
        g_partials[b] = fin - gold;
    }

    // fused deterministic batch reduction (last block)
    if (tid < 32) {
        int old = 0;
        if (tid == 0) {
            __threadfence();
            old = atomicAdd(&g_ctr, 1);
        }
        old = __shfl_sync(0xffffffffu, old, 0);
        if (old == BB - 1) {
            __threadfence();
            float v = g_partials[tid];
            #pragma unroll
            for (int o = 16; o; o >>= 1) v += __shfl_down_sync(0xffffffffu, v, o);
            if (tid == 0) { out[0] = v / (float)BB; g_ctr = 0; }
        }
    }
}

extern "C" void kernel_launch(void* const* d_in, const int* in_sizes, int n_in,
                              void* d_out, int out_size)
{
    const float* feat    = (const float*)d_in[0];
    const int*   targets = (const int*)d_in[1];
    const int*   lengths = (const int*)d_in[2];
    float*       out     = (float*)d_out;

    const int smem_bytes = NB * TILESZ * 4 + 2 * KK * 4 + TT * 4;  // ~67 KB
    cudaFuncSetAttribute(crf_fwd_kernel, cudaFuncAttributeMaxDynamicSharedMemorySize, smem_bytes);
    crf_fwd_kernel<<<BB, NTH, smem_bytes>>>(feat, targets, lengths, out);
}

// round 15
// speedup vs baseline: 1.3080x; 1.1757x over previous
#include <cuda_runtime.h>
#include <cuda_fp16.h>
#include <cstdint>

#define BB 32
#define TT 512
#define KK 48
#define TILESZ (KK * KK)     // 2304 words, contiguous (SROW = 48, no padding)
#define NTH 96               // 3 warps -> 1 per SMSP
#define NB 6
#define START_TAG 46
#define STOP_TAG 47

__device__ float g_partials[BB];
__device__ int   g_ctr = 0;

__device__ __forceinline__ float ex2f(float x) {
    float y; asm("ex2.approx.ftz.f32 %0, %1;" : "=f"(y) : "f"(x)); return y;
}
__device__ __forceinline__ float lg2f(float x) {
    float y; asm("lg2.approx.ftz.f32 %0, %1;" : "=f"(y) : "f"(x)); return y;
}
__device__ __forceinline__ void cp16(uint32_t smem, const void* g) {
    asm volatile("cp.async.cg.shared.global [%0], [%1], 16;" :: "r"(smem), "l"(g));
}
__device__ __forceinline__ void cp_commit() { asm volatile("cp.async.commit_group;"); }
__device__ __forceinline__ void cp_wait3()  { asm volatile("cp.async.wait_group 3;"); }
__device__ __forceinline__ void cp_wait4()  { asm volatile("cp.async.wait_group 4;"); }

// pack two fp32 to f16x2, multiply by log2e in half, then 2^x via one MUFU op
__device__ __forceinline__ uint32_t ex2_cvt(float f0, float f1, uint32_t l2e2) {
    uint32_t p, r;
    asm("cvt.rn.f16x2.f32 %0, %1, %2;" : "=r"(p) : "f"(f1), "f"(f0));  // hi=f1, lo=f0
    asm("mul.f16x2 %0, %0, %1;" : "+r"(p) : "r"(l2e2));
    asm volatile("ex2.approx.f16x2 %0, %1;" : "=r"(r) : "r"(p));
    return r;
}
__device__ __forceinline__ uint32_t hfma2(uint32_t a, uint32_t b, uint32_t c) {
    uint32_t d; asm("fma.rn.f16x2 %0, %1, %2, %3;" : "=r"(d) : "r"(a), "r"(b), "r"(c)); return d;
}
__device__ __forceinline__ uint32_t hmul2(uint32_t a, uint32_t b) {
    uint32_t d; asm("mul.f16x2 %0, %1, %2;" : "=r"(d) : "r"(a), "r"(b)); return d;
}
__device__ __forceinline__ uint32_t hadd2(uint32_t a, uint32_t b) {
    uint32_t d; asm("add.f16x2 %0, %1, %2;" : "=r"(d) : "r"(a), "r"(b)); return d;
}
__device__ __forceinline__ uint32_t prmt(uint32_t a, uint32_t sel) {
    uint32_t d; asm("prmt.b32 %0, %1, %1, %2;" : "=r"(d) : "r"(a), "r"(sel)); return d;
}

extern __shared__ float smem_dyn[];

__global__ __launch_bounds__(NTH, 1)
void crf_fwd_kernel(const float* __restrict__ feat,
                    const int*   __restrict__ targets,
                    const int*   __restrict__ lengths,
                    float*       __restrict__ out)
{
    float*    tile = smem_dyn;                         // NB * TILESZ fp32 (contiguous)
    uint32_t* ch   = (uint32_t*)(tile + NB * TILESZ);  // 2 x 48 packed (c,c) f16x2
    int*      tsh  = (int*)(ch + 2 * KK);              // TT raw target indices

    const int b   = blockIdx.x;
    const int tid = threadIdx.x;
    const int len = lengths[b];
    const float* fb = feat + (size_t)b * TT * (KK * KK);

    for (int i = tid; i < TT; i += NTH) tsh[i] = targets[b * TT + i];

    // lane owns column pair p = 8w + (l&7) -> cols 2p, 2p+1; i = u + 4*ii, u = l>>3
    const int l = tid & 31;
    const int w = tid >> 5;
    const int p = 8 * w + (l & 7);
    const int u = l >> 3;

    const uint32_t L2E2 = 0x3DC53DC5u;   // half(log2e) duplicated

    uint32_t sb[NB];
    #pragma unroll
    for (int n = 0; n < NB; ++n)
        sb[n] = (uint32_t)__cvta_generic_to_shared(tile + n * TILESZ);

    const float LN2 = 0.6931471805599453f;

    // Prologue: issue tiles 0..4 as 5 groups (6 contiguous 16B chunks/thread)
    #pragma unroll
    for (int tt = 0; tt < 5; ++tt) {
        if (tt < len) {
            const float* src = fb + (size_t)tt * TILESZ;
            #pragma unroll
            for (int q = 0; q < 6; ++q)
                cp16(sb[tt] + (tid + q * NTH) * 16, src + (tid + q * NTH) * 4);
        }
        cp_commit();
    }
    cp_wait4();
    __syncthreads();       // tile 0 visible

    // init packed carries s_0 = c_0 * 2^-4  (N_0 = 2^4), buffer 0
    if (tid < KK) {
        float c = ex2f(tile[KK * START_TAG + tid] * 1.4426950408889634f);
        __half h = __float2half_rn(c * 0.0625f);
        uint32_t hb = (uint32_t)__half_as_ushort(h);
        ch[tid] = hb | (hb << 16);
    }
    float gold = 0.f;
    int   eacc = 0;
    if (tid == 0) gold = tile[tsh[0]];

    cp_wait3();
    __syncthreads();       // tile 1 visible

    // E for tile 1 (24 elements = 12 packed f16x2: i = u + 4*ii, cols 2p, 2p+1)
    uint32_t E2[12];
    {
        const float* fn = tile + 1 * TILESZ + u * KK + 2 * p;
        #pragma unroll
        for (int ii = 0; ii < 12; ++ii) {
            float2 f = *(const float2*)(fn + KK * 4 * ii);
            E2[ii] = ex2_cvt(f.x, f.y, L2E2);
        }
    }
    if (5 < len) {
        const float* src = fb + (size_t)5 * TILESZ;
        #pragma unroll
        for (int q = 0; q < 6; ++q)
            cp16(sb[5] + (tid + q * NTH) * 16, src + (tid + q * NTH) * 4);
    }
    cp_commit();

    int cur = 1;   // t % NB
    int pfb = 0;   // (t+5) % NB
    for (int t = 1; t < len; ++t) {
        cp_wait3();
        __syncthreads();     // carries(t-1) + tile t+1 visible; buffer pfb drained

        // prefetch tile t+5
        {
            int tn = t + 5;
            if (tn < len) {
                const float* src = fb + (size_t)tn * TILESZ;
                uint32_t dst = sb[pfb];
                #pragma unroll
                for (int q = 0; q < 6; ++q)
                    cp16(dst + (tid + q * NTH) * 16, src + (tid + q * NTH) * 4);
            }
            cp_commit();
        }

        const int prev = (t - 1) & 1;
        const uint32_t* cr = ch + prev * KK;

        // lagged renorm, target T = -8: rsc = 2^(-8 - (be-15)); f16 field = 22 - be
        const uint32_t ch0 = cr[0];
        const int be = (int)((ch0 >> 10) & 31);
        const uint32_t rb = (uint32_t)(22 - be) << 10;
        const uint32_t rsc2 = rb | (rb << 16);
        eacc += be;

        // dot over 12 i-values (i = u + 4*ii), both columns at once
        uint32_t aa = hmul2(E2[0], cr[u]);
        uint32_t bb = hmul2(E2[1], cr[u + 4]);
        aa = hfma2(E2[2],  cr[u + 8],  aa);
        bb = hfma2(E2[3],  cr[u + 12], bb);
        aa = hfma2(E2[4],  cr[u + 16], aa);
        bb = hfma2(E2[5],  cr[u + 20], bb);
        aa = hfma2(E2[6],  cr[u + 24], aa);
        bb = hfma2(E2[7],  cr[u + 28], bb);
        aa = hfma2(E2[8],  cr[u + 32], aa);
        bb = hfma2(E2[9],  cr[u + 36], bb);
        aa = hfma2(E2[10], cr[u + 40], aa);
        bb = hfma2(E2[11], cr[u + 44], bb);
        uint32_t acc = hadd2(aa, bb);

        if (tid == 0) gold += tile[cur * TILESZ + tsh[t]];

        // E for tile t+1 (pinned EX2 pre-barrier; dead at t = len-1, harmless)
        {
            const float* fn = tile + ((cur + 1 == NB) ? 0 : cur + 1) * TILESZ + u * KK + 2 * p;
            #pragma unroll
            for (int ii = 0; ii < 12; ++ii) {
                float2 f = *(const float2*)(fn + KK * 4 * ii);
                E2[ii] = ex2_cvt(f.x, f.y, L2E2);
            }
        }

        // reduce over u (lanes differing in bits 3,4), both columns simultaneously
        acc = hadd2(acc, __shfl_xor_sync(0xffffffffu, acc, 8));
        acc = hadd2(acc, __shfl_xor_sync(0xffffffffu, acc, 16));

        if (u == 0) {
            acc = hmul2(acc, rsc2);
            uint32_t d0 = prmt(acc, 0x1010);   // (lo,lo) -> col 2p
            uint32_t d1 = prmt(acc, 0x3232);   // (hi,hi) -> col 2p+1
            *(uint2*)(ch + (t & 1) * KK + 2 * p) = make_uint2(d0, d1);
        }

        if (++cur == NB) cur = 0;
        if (++pfb == NB) pfb = 0;
    }

    __syncthreads();
    if (tid == 0) {
        // ledger: lg2(c_last[stop]) = lg2(s_last[stop]) + 4 + sum(be) - 7*(len-1)
        uint32_t sw = ch[((len - 1) & 1) * KK + STOP_TAG];
        float s = __half2float(__ushort_as_half((unsigned short)(sw & 0xFFFF)));
        float fin = (lg2f(s) + 4.0f + (float)eacc - 7.0f * (float)(len - 1)) * LN2;
        g_partials[b] = fin - gold;
    }

    // fused deterministic batch reduction (last block)
    if (tid < 32) {
        int old = 0;
        if (tid == 0) {
            __threadfence();
            old = atomicAdd(&g_ctr, 1);
        }
        old = __shfl_sync(0xffffffffu, old, 0);
        if (old == BB - 1) {
            __threadfence();
            float v = g_partials[tid];
            #pragma unroll
            for (int o = 16; o; o >>= 1) v += __shfl_down_sync(0xffffffffu, v, o);
            if (tid == 0) { out[0] = v / (float)BB; g_ctr = 0; }
        }
    }
}

extern "C" void kernel_launch(void* const* d_in, const int* in_sizes, int n_in,
                              void* d_out, int out_size)
{
    const float* feat    = (const float*)d_in[0];
    const int*   targets = (const int*)d_in[1];
    const int*   lengths = (const int*)d_in[2];
    float*       out     = (float*)d_out;

    const int smem_bytes = NB * TILESZ * 4 + 2 * KK * 4 + TT * 4;  // ~57.8 KB
    cudaFuncSetAttribute(crf_fwd_kernel, cudaFuncAttributeMaxDynamicSharedMemorySize, smem_bytes);
    crf_fwd_kernel<<<BB, NTH, smem_bytes>>>(feat, targets, lengths, out);
}